// round 3
// baseline (speedup 1.0000x reference)
#include <cuda_runtime.h>
#include <mma.h>
#include <cstdint>

using namespace nvcuda;

// Problem constants (fixed by the reference)
#define TOK   16384       // B*N tokens
#define DIM   1024        // D
#define HID   2048        // 2*D
#define NE    8           // experts
#define BM    128         // GEMM row tile
#define BN    64          // GEMM col tile
#define BK    16          // GEMM k tile
#define NTHR  256
#define ROWTILES ((2*TOK + NE*BM)/BM)   // 264 fixed row tiles over padded assignment space

// ---------------- device scratch (no allocations allowed) ----------------
__device__ int   g_count[NE];
__device__ int   g_poff[NE+1];                // BM-padded exclusive offsets
__device__ int   g_perm[NE*TOK];              // token id per (expert, pos)
__device__ float g_gate[NE*TOK];              // gate per (expert, pos)
__device__ float g_H[(size_t)(2*TOK + NE*BM) * HID];   // padded hidden activations

// ---------------- async copy helpers ----------------
__device__ __forceinline__ void cp_async16(void* dst, const void* src) {
  uint32_t s = (uint32_t)__cvta_generic_to_shared(dst);
  asm volatile("cp.async.cg.shared.global [%0], [%1], 16;" :: "r"(s), "l"(src));
}
#define CP_COMMIT() asm volatile("cp.async.commit_group;")
#define CP_WAIT(N)  asm volatile("cp.async.wait_group %0;" :: "n"(N))

// ---------------- kernel 0: zero output + counts ----------------
__global__ void k_zero(float* __restrict__ out, int n4) {
  float4 z = make_float4(0.f, 0.f, 0.f, 0.f);
  float4* o = (float4*)out;
  for (int i = blockIdx.x * blockDim.x + threadIdx.x; i < n4; i += gridDim.x * blockDim.x)
    o[i] = z;
  if (blockIdx.x == 0 && threadIdx.x < NE) g_count[threadIdx.x] = 0;
}

// ---------------- kernel 1: router (logits -> top2 -> softmax -> buckets) ----------------
__global__ __launch_bounds__(256) void k_router(const float* __restrict__ x,
                                                const float* __restrict__ Wg,
                                                const float* __restrict__ bg)
{
  __shared__ float sWg[DIM * NE];   // 32 KB
  const int tid = threadIdx.x;
  for (int i = tid; i < (DIM * NE) / 4; i += 256)
    ((float4*)sWg)[i] = ((const float4*)Wg)[i];
  __syncthreads();

  const int warp = tid >> 5, lane = tid & 31;
  const int t = blockIdx.x * 8 + warp;
  const float* xr = x + (size_t)t * DIM;

  float acc[NE];
#pragma unroll
  for (int e = 0; e < NE; ++e) acc[e] = 0.f;
  for (int d = lane; d < DIM; d += 32) {
    float xv = xr[d];
    const float* w = sWg + d * NE;
#pragma unroll
    for (int e = 0; e < NE; ++e) acc[e] += xv * w[e];
  }
#pragma unroll
  for (int o = 16; o > 0; o >>= 1)
#pragma unroll
    for (int e = 0; e < NE; ++e) acc[e] += __shfl_down_sync(0xffffffffu, acc[e], o);

  if (lane == 0) {
#pragma unroll
    for (int e = 0; e < NE; ++e) acc[e] += bg[e];
    // top-1 (ties -> lowest index, matches lax.top_k)
    int i1 = 0; float l1 = acc[0];
#pragma unroll
    for (int e = 1; e < NE; ++e) if (acc[e] > l1) { l1 = acc[e]; i1 = e; }
    int i2 = -1; float l2 = -3.4e38f;
#pragma unroll
    for (int e = 0; e < NE; ++e) if (e != i1 && acc[e] > l2) { l2 = acc[e]; i2 = e; }
    // softmax over [l1, l2], l1 >= l2
    float ex  = __expf(l2 - l1);
    float inv = 1.0f / (1.0f + ex);
    int p1 = atomicAdd(&g_count[i1], 1);
    g_perm[i1 * TOK + p1] = t; g_gate[i1 * TOK + p1] = inv;
    int p2 = atomicAdd(&g_count[i2], 1);
    g_perm[i2 * TOK + p2] = t; g_gate[i2 * TOK + p2] = ex * inv;
  }
}

// ---------------- kernel 2: padded-offset scan (tiny) ----------------
__global__ void k_scan() {
  if (threadIdx.x == 0) {
    int off = 0;
#pragma unroll
    for (int e = 0; e < NE; ++e) {
      g_poff[e] = off;
      off += ((g_count[e] + BM - 1) / BM) * BM;
    }
    g_poff[NE] = off;
  }
}

// ---------------- kernel 3: FFN layer 1  H = relu(gather(x) @ W1[e] + b1[e]) ----------------
__global__ __launch_bounds__(NTHR) void k_ffn1(const float* __restrict__ x,
                                               const float* __restrict__ W1,
                                               const float* __restrict__ b1)
{
  __shared__ float sm[2*BM*BK + 2*BK*BN];   // 24 KB double-buffered stages (reused as epilogue scratch)
  __shared__ int   sTok[BM];

  const int tileStart = blockIdx.y * BM;
  if (tileStart >= g_poff[NE]) return;
  int e = 0;
#pragma unroll
  for (int i = 1; i < NE; ++i) if (tileStart >= g_poff[i]) e = i;
  const int posBase = tileStart - g_poff[e];
  const int cnt = g_count[e];
  const int tid = threadIdx.x;

  for (int r = tid; r < BM; r += NTHR) {
    int p = posBase + r;
    sTok[r] = g_perm[e * TOK + (p < cnt ? p : posBase)];   // pad rows read a valid token (finite garbage)
  }
  __syncthreads();

  const int cBase = blockIdx.x * BN;
  const float* Bp = W1 + (size_t)e * DIM * HID;
  float* const As0 = sm;
  float* const Bs0 = sm + 2*BM*BK;

  wmma::fragment<wmma::accumulator,16,16,8,float> acc[2][2];
#pragma unroll
  for (int i = 0; i < 2; ++i)
#pragma unroll
    for (int j = 0; j < 2; ++j) wmma::fill_fragment(acc[i][j], 0.0f);

  const int warpId = tid >> 5, lane = tid & 31;
  const int wm = warpId & 3, wn = warpId >> 2;   // 4x2 warp grid, 32x32 warp tile

  auto load_tile = [&](int stage, int kt) {
    float* As = As0 + stage * (BM*BK);
    float* Bs = Bs0 + stage * (BK*BN);
    const int k0 = kt * BK;
#pragma unroll
    for (int c = tid; c < (BM*BK)/4; c += NTHR) {          // 512 16B chunks
      int row = c >> 2, seg = c & 3;
      cp_async16(As + row*BK + seg*4, x + (size_t)sTok[row]*DIM + k0 + seg*4);
    }
    { int row = tid >> 4, seg = tid & 15;                  // 256 chunks
      cp_async16(Bs + row*BN + seg*4, Bp + (size_t)(k0+row)*HID + cBase + seg*4); }
    CP_COMMIT();
  };

  const int KT = DIM / BK;   // 64
  load_tile(0, 0);
  for (int kt = 0; kt < KT; ++kt) {
    if (kt + 1 < KT) { load_tile((kt+1)&1, kt+1); CP_WAIT(1); }
    else             { CP_WAIT(0); }
    __syncthreads();
    const float* As = As0 + (kt&1)*(BM*BK);
    const float* Bs = Bs0 + (kt&1)*(BK*BN);
#pragma unroll
    for (int kk = 0; kk < BK; kk += 8) {
      wmma::fragment<wmma::matrix_a,16,16,8,wmma::precision::tf32,wmma::row_major> a0, a1;
      wmma::fragment<wmma::matrix_b,16,16,8,wmma::precision::tf32,wmma::row_major> b0, b1f;
      wmma::load_matrix_sync(a0,  As + (wm*32     )*BK + kk, BK);
      wmma::load_matrix_sync(a1,  As + (wm*32 + 16)*BK + kk, BK);
      wmma::load_matrix_sync(b0,  Bs + kk*BN + wn*32,        BN);
      wmma::load_matrix_sync(b1f, Bs + kk*BN + wn*32 + 16,   BN);
#pragma unroll
      for (int i = 0; i < 4; ++i) { a0.x[i] = wmma::__float_to_tf32(a0.x[i]);
                                    a1.x[i] = wmma::__float_to_tf32(a1.x[i]);
                                    b0.x[i] = wmma::__float_to_tf32(b0.x[i]);
                                    b1f.x[i]= wmma::__float_to_tf32(b1f.x[i]); }
      wmma::mma_sync(acc[0][0], a0, b0,  acc[0][0]);
      wmma::mma_sync(acc[0][1], a0, b1f, acc[0][1]);
      wmma::mma_sync(acc[1][0], a1, b0,  acc[1][0]);
      wmma::mma_sync(acc[1][1], a1, b1f, acc[1][1]);
    }
    __syncthreads();
  }

  // epilogue: +b1, relu, store ALL 128 rows into padded H (pad rows never reach the output)
  const float bv = b1[(size_t)e*HID + cBase + wn*32 + lane];
  float* scr = sm + wm * (32*36);
#pragma unroll
  for (int round = 0; round < 2; ++round) {
    if (wn == round) {
      wmma::store_matrix_sync(scr,              acc[0][0], 36, wmma::mem_row_major);
      wmma::store_matrix_sync(scr + 16,         acc[0][1], 36, wmma::mem_row_major);
      wmma::store_matrix_sync(scr + 16*36,      acc[1][0], 36, wmma::mem_row_major);
      wmma::store_matrix_sync(scr + 16*36 + 16, acc[1][1], 36, wmma::mem_row_major);
      __syncwarp();
      float* Hp = g_H + (size_t)(tileStart + wm*32)*HID + cBase + wn*32 + lane;
#pragma unroll 8
      for (int r = 0; r < 32; ++r)
        Hp[(size_t)r * HID] = fmaxf(scr[r*36 + lane] + bv, 0.0f);
    }
    __syncthreads();
  }
}

// ---------------- kernel 4: FFN layer 2  out[token] += gate * (H @ W2[e] + b2[e]) ----------------
__global__ __launch_bounds__(NTHR) void k_ffn2(const float* __restrict__ W2,
                                               const float* __restrict__ b2,
                                               float* __restrict__ out)
{
  __shared__ float sm[2*BM*BK + 2*BK*BN];
  __shared__ int   sTok[BM];
  __shared__ float sGate[BM];

  const int tileStart = blockIdx.y * BM;
  if (tileStart >= g_poff[NE]) return;
  int e = 0;
#pragma unroll
  for (int i = 1; i < NE; ++i) if (tileStart >= g_poff[i]) e = i;
  const int posBase = tileStart - g_poff[e];
  const int cnt = g_count[e];
  const int tid = threadIdx.x;

  for (int r = tid; r < BM; r += NTHR) {
    int p = posBase + r;
    bool act = p < cnt;
    sTok[r]  = act ? g_perm[e * TOK + p] : -1;
    sGate[r] = act ? g_gate[e * TOK + p] : 0.0f;
  }
  __syncthreads();

  const int cBase = blockIdx.x * BN;
  const float* Bp = W2 + (size_t)e * HID * DIM;
  const float* Ap = g_H + (size_t)tileStart * HID;
  float* const As0 = sm;
  float* const Bs0 = sm + 2*BM*BK;

  wmma::fragment<wmma::accumulator,16,16,8,float> acc[2][2];
#pragma unroll
  for (int i = 0; i < 2; ++i)
#pragma unroll
    for (int j = 0; j < 2; ++j) wmma::fill_fragment(acc[i][j], 0.0f);

  const int warpId = tid >> 5, lane = tid & 31;
  const int wm = warpId & 3, wn = warpId >> 2;

  auto load_tile = [&](int stage, int kt) {
    float* As = As0 + stage * (BM*BK);
    float* Bs = Bs0 + stage * (BK*BN);
    const int k0 = kt * BK;
#pragma unroll
    for (int c = tid; c < (BM*BK)/4; c += NTHR) {
      int row = c >> 2, seg = c & 3;
      cp_async16(As + row*BK + seg*4, Ap + (size_t)row*HID + k0 + seg*4);
    }
    { int row = tid >> 4, seg = tid & 15;
      cp_async16(Bs + row*BN + seg*4, Bp + (size_t)(k0+row)*DIM + cBase + seg*4); }
    CP_COMMIT();
  };

  const int KT = HID / BK;   // 128
  load_tile(0, 0);
  for (int kt = 0; kt < KT; ++kt) {
    if (kt + 1 < KT) { load_tile((kt+1)&1, kt+1); CP_WAIT(1); }
    else             { CP_WAIT(0); }
    __syncthreads();
    const float* As = As0 + (kt&1)*(BM*BK);
    const float* Bs = Bs0 + (kt&1)*(BK*BN);
#pragma unroll
    for (int kk = 0; kk < BK; kk += 8) {
      wmma::fragment<wmma::matrix_a,16,16,8,wmma::precision::tf32,wmma::row_major> a0, a1;
      wmma::fragment<wmma::matrix_b,16,16,8,wmma::precision::tf32,wmma::row_major> b0, b1f;
      wmma::load_matrix_sync(a0,  As + (wm*32     )*BK + kk, BK);
      wmma::load_matrix_sync(a1,  As + (wm*32 + 16)*BK + kk, BK);
      wmma::load_matrix_sync(b0,  Bs + kk*BN + wn*32,        BN);
      wmma::load_matrix_sync(b1f, Bs + kk*BN + wn*32 + 16,   BN);
#pragma unroll
      for (int i = 0; i < 4; ++i) { a0.x[i] = wmma::__float_to_tf32(a0.x[i]);
                                    a1.x[i] = wmma::__float_to_tf32(a1.x[i]);
                                    b0.x[i] = wmma::__float_to_tf32(b0.x[i]);
                                    b1f.x[i]= wmma::__float_to_tf32(b1f.x[i]); }
      wmma::mma_sync(acc[0][0], a0, b0,  acc[0][0]);
      wmma::mma_sync(acc[0][1], a0, b1f, acc[0][1]);
      wmma::mma_sync(acc[1][0], a1, b0,  acc[1][0]);
      wmma::mma_sync(acc[1][1], a1, b1f, acc[1][1]);
    }
    __syncthreads();
  }

  // epilogue: gate * (acc + b2) scatter-added into out (guarded against pad rows)
  const float bv = b2[(size_t)e*DIM + cBase + wn*32 + lane];
  float* scr = sm + wm * (32*36);
#pragma unroll
  for (int round = 0; round < 2; ++round) {
    if (wn == round) {
      wmma::store_matrix_sync(scr,              acc[0][0], 36, wmma::mem_row_major);
      wmma::store_matrix_sync(scr + 16,         acc[0][1], 36, wmma::mem_row_major);
      wmma::store_matrix_sync(scr + 16*36,      acc[1][0], 36, wmma::mem_row_major);
      wmma::store_matrix_sync(scr + 16*36 + 16, acc[1][1], 36, wmma::mem_row_major);
      __syncwarp();
#pragma unroll 4
      for (int r = 0; r < 32; ++r) {
        int rr = wm*32 + r;
        int tokv = sTok[rr];
        if (tokv >= 0) {
          atomicAdd(out + (size_t)tokv*DIM + cBase + wn*32 + lane,
                    sGate[rr] * (scr[r*36 + lane] + bv));
        }
      }
    }
    __syncthreads();
  }
}

// ---------------- launcher ----------------
extern "C" void kernel_launch(void* const* d_in, const int* in_sizes, int n_in,
                              void* d_out, int out_size) {
  const float* x  = (const float*)d_in[0];
  const float* Wg = (const float*)d_in[1];
  const float* bg = (const float*)d_in[2];
  const float* W1 = (const float*)d_in[3];
  const float* b1 = (const float*)d_in[4];
  const float* W2 = (const float*)d_in[5];
  const float* b2 = (const float*)d_in[6];
  float* out = (float*)d_out;
  (void)in_sizes; (void)n_in;

  k_zero<<<2048, 256>>>(out, out_size / 4);
  k_router<<<TOK / 8, 256>>>(x, Wg, bg);
  k_scan<<<1, 32>>>();
  dim3 g1(HID / BN, ROWTILES);   // 32 x 264
  k_ffn1<<<g1, NTHR>>>(x, W1, b1);
  dim3 g2(DIM / BN, ROWTILES);   // 16 x 264
  k_ffn2<<<g2, NTHR>>>(W2, b2, out);
}

// round 4
// speedup vs baseline: 1.3528x; 1.3528x over previous
#include <cuda_runtime.h>
#include <mma.h>
#include <cstdint>

using namespace nvcuda;

// Problem constants (fixed by the reference)
#define TOK   16384       // B*N tokens
#define DIM   1024        // D
#define HID   2048        // 2*D
#define NE    8           // experts
#define BM    128         // GEMM row tile
#define BN    128         // GEMM col tile
#define BK    16          // GEMM k tile
#define NTHR  128         // 4 warps, 2x2 warp grid, 64x64 warp tiles
#define SA    20          // A smem row stride (floats), 80B = 16B aligned, depadded
#define SB    132         // B smem row stride (floats), 528B = 16B aligned
#define ROWTILES ((2*TOK + NE*BM)/BM)   // 264 fixed row tiles over padded space
#define PADROWS  (2*TOK + NE*BM)        // 34432

// ---------------- device scratch (no allocations allowed) ----------------
__device__ int   g_count[NE];
__device__ int   g_poff[NE+1];                 // BM-padded exclusive offsets
__device__ int   g_perm[NE*TOK];               // token id per (expert, pos)
__device__ float g_gate[NE*TOK];               // gate per (expert, pos)
__device__ int   g_slot1[TOK];                 // e*TOK+p of top-1 assignment
__device__ int   g_slot2[TOK];                 // e*TOK+p of top-2 assignment
__device__ float g_X  [(size_t)TOK * DIM];     // tf32-rounded x
__device__ float g_W1r[(size_t)NE * DIM * HID];
__device__ float g_W2r[(size_t)NE * HID * DIM];
__device__ float g_H  [(size_t)PADROWS * HID]; // padded hidden (tf32-rounded)
__device__ float g_Y  [(size_t)PADROWS * DIM]; // gated expert outputs (padded rows)

// ---------------- async copy helpers ----------------
__device__ __forceinline__ void cp_async16(void* dst, const void* src) {
  uint32_t s = (uint32_t)__cvta_generic_to_shared(dst);
  asm volatile("cp.async.cg.shared.global [%0], [%1], 16;" :: "r"(s), "l"(src));
}
#define CP_COMMIT() asm volatile("cp.async.commit_group;")
#define CP_WAIT(N)  asm volatile("cp.async.wait_group %0;" :: "n"(N))

// ---------------- kernel: zero expert counts ----------------
__global__ void k_init() {
  if (threadIdx.x < NE) g_count[threadIdx.x] = 0;
}

// ---------------- kernel: tf32-round an array (float4 grid-stride) ----------------
__global__ void k_round(float* __restrict__ dst, const float* __restrict__ src, int n4) {
  const float4* s = (const float4*)src;
  float4* d = (float4*)dst;
  for (int i = blockIdx.x * blockDim.x + threadIdx.x; i < n4; i += gridDim.x * blockDim.x) {
    float4 v = s[i];
    v.x = wmma::__float_to_tf32(v.x);
    v.y = wmma::__float_to_tf32(v.y);
    v.z = wmma::__float_to_tf32(v.z);
    v.w = wmma::__float_to_tf32(v.w);
    d[i] = v;
  }
}

// ---------------- router: logits -> top2 -> softmax -> buckets; also rounds x ----------------
__global__ __launch_bounds__(256) void k_router(const float* __restrict__ x,
                                                const float* __restrict__ Wg,
                                                const float* __restrict__ bg)
{
  __shared__ float sWg[DIM * NE];   // 32 KB
  const int tid = threadIdx.x;
  for (int i = tid; i < (DIM * NE) / 4; i += 256)
    ((float4*)sWg)[i] = ((const float4*)Wg)[i];
  __syncthreads();

  const int warp = tid >> 5, lane = tid & 31;
  const int t = blockIdx.x * 8 + warp;
  const float* xr = x + (size_t)t * DIM;
  float* xw = g_X + (size_t)t * DIM;

  float acc[NE];
#pragma unroll
  for (int e = 0; e < NE; ++e) acc[e] = 0.f;
  for (int d = lane; d < DIM; d += 32) {
    float xv = xr[d];
    xw[d] = wmma::__float_to_tf32(xv);          // fused tf32 rounding pass
    const float* w = sWg + d * NE;
#pragma unroll
    for (int e = 0; e < NE; ++e) acc[e] += xv * w[e];
  }
#pragma unroll
  for (int o = 16; o > 0; o >>= 1)
#pragma unroll
    for (int e = 0; e < NE; ++e) acc[e] += __shfl_down_sync(0xffffffffu, acc[e], o);

  if (lane == 0) {
#pragma unroll
    for (int e = 0; e < NE; ++e) acc[e] += bg[e];
    int i1 = 0; float l1 = acc[0];
#pragma unroll
    for (int e = 1; e < NE; ++e) if (acc[e] > l1) { l1 = acc[e]; i1 = e; }
    int i2 = -1; float l2 = -3.4e38f;
#pragma unroll
    for (int e = 0; e < NE; ++e) if (e != i1 && acc[e] > l2) { l2 = acc[e]; i2 = e; }
    float ex  = __expf(l2 - l1);
    float inv = 1.0f / (1.0f + ex);
    int p1 = atomicAdd(&g_count[i1], 1);
    g_perm[i1 * TOK + p1] = t; g_gate[i1 * TOK + p1] = inv;
    g_slot1[t] = i1 * TOK + p1;
    int p2 = atomicAdd(&g_count[i2], 1);
    g_perm[i2 * TOK + p2] = t; g_gate[i2 * TOK + p2] = ex * inv;
    g_slot2[t] = i2 * TOK + p2;
  }
}

// ---------------- padded-offset scan (tiny) ----------------
__global__ void k_scan() {
  if (threadIdx.x == 0) {
    int off = 0;
#pragma unroll
    for (int e = 0; e < NE; ++e) {
      g_poff[e] = off;
      off += ((g_count[e] + BM - 1) / BM) * BM;
    }
    g_poff[NE] = off;
  }
}

// ---------------- FFN layer 1: H = tf32(relu(gather(X) @ W1[e] + b1[e])) ----------------
__global__ __launch_bounds__(NTHR) void k_ffn1(const float* __restrict__ b1)
{
  __shared__ __align__(16) float sm[2*BM*SA + 2*BK*SB];   // 37.4 KB, reused as epilogue scratch
  __shared__ int sTok[BM];

  const int tileStart = blockIdx.y * BM;
  if (tileStart >= g_poff[NE]) return;
  int e = 0;
#pragma unroll
  for (int i = 1; i < NE; ++i) if (tileStart >= g_poff[i]) e = i;
  const int posBase = tileStart - g_poff[e];
  const int cnt = g_count[e];
  const int tid = threadIdx.x;

  for (int r = tid; r < BM; r += NTHR) {
    int p = posBase + r;
    sTok[r] = g_perm[e * TOK + (p < cnt ? p : cnt - 1)];  // pad rows: valid token, finite garbage
  }
  __syncthreads();

  const int cBase = blockIdx.x * BN;
  const float* Bp = g_W1r + (size_t)e * DIM * HID;
  float* const As0 = sm;
  float* const Bs0 = sm + 2*BM*SA;

  wmma::fragment<wmma::accumulator,16,16,8,float> acc[4][4];
#pragma unroll
  for (int i = 0; i < 4; ++i)
#pragma unroll
    for (int j = 0; j < 4; ++j) wmma::fill_fragment(acc[i][j], 0.0f);

  const int warpId = tid >> 5, lane = tid & 31;
  const int wm = warpId & 1, wn = warpId >> 1;   // 2x2 warp grid, 64x64 warp tiles

  auto load_tile = [&](int stage, int kt) {
    float* As = As0 + stage * (BM*SA);
    float* Bs = Bs0 + stage * (BK*SB);
    const int k0 = kt * BK;
#pragma unroll
    for (int c = tid; c < (BM*BK)/4; c += NTHR) {          // 512 chunks of 16B
      int row = c >> 2, seg = c & 3;
      cp_async16(As + row*SA + seg*4, g_X + (size_t)sTok[row]*DIM + k0 + seg*4);
    }
#pragma unroll
    for (int c = tid; c < (BK*BN)/4; c += NTHR) {          // 512 chunks
      int row = c >> 5, seg = c & 31;
      cp_async16(Bs + row*SB + seg*4, Bp + (size_t)(k0+row)*HID + cBase + seg*4);
    }
    CP_COMMIT();
  };

  const int KT = DIM / BK;   // 64
  load_tile(0, 0);
  for (int kt = 0; kt < KT; ++kt) {
    if (kt + 1 < KT) { load_tile((kt+1)&1, kt+1); CP_WAIT(1); }
    else             { CP_WAIT(0); }
    __syncthreads();
    const float* As = As0 + (kt&1)*(BM*SA);
    const float* Bs = Bs0 + (kt&1)*(BK*SB);
#pragma unroll
    for (int kk = 0; kk < BK; kk += 8) {
      wmma::fragment<wmma::matrix_a,16,16,8,wmma::precision::tf32,wmma::row_major> af[4];
      wmma::fragment<wmma::matrix_b,16,16,8,wmma::precision::tf32,wmma::row_major> bf[4];
#pragma unroll
      for (int mi = 0; mi < 4; ++mi)
        wmma::load_matrix_sync(af[mi], As + (wm*64 + mi*16)*SA + kk, SA);
#pragma unroll
      for (int ni = 0; ni < 4; ++ni)
        wmma::load_matrix_sync(bf[ni], Bs + kk*SB + wn*64 + ni*16, SB);
      // data pre-rounded to tf32 -> no per-element conversion needed
#pragma unroll
      for (int mi = 0; mi < 4; ++mi)
#pragma unroll
        for (int ni = 0; ni < 4; ++ni)
          wmma::mma_sync(acc[mi][ni], af[mi], bf[ni], acc[mi][ni]);
    }
    __syncthreads();
  }

  // epilogue: +b1, relu, tf32-round, store all 128 rows into padded H
  float* scr = sm + warpId * (32*36);     // 4.6KB per warp, disjoint
#pragma unroll
  for (int h = 0; h < 2; ++h) {
#pragma unroll
    for (int g = 0; g < 2; ++g) {
      wmma::store_matrix_sync(scr,              acc[2*h  ][2*g  ], 36, wmma::mem_row_major);
      wmma::store_matrix_sync(scr + 16,         acc[2*h  ][2*g+1], 36, wmma::mem_row_major);
      wmma::store_matrix_sync(scr + 16*36,      acc[2*h+1][2*g  ], 36, wmma::mem_row_major);
      wmma::store_matrix_sync(scr + 16*36 + 16, acc[2*h+1][2*g+1], 36, wmma::mem_row_major);
      __syncwarp();
      const int col = cBase + wn*64 + g*32 + lane;
      const float bv = b1[(size_t)e*HID + col];
      float* Hp = g_H + (size_t)(tileStart + wm*64 + h*32)*HID + col;
#pragma unroll 8
      for (int r = 0; r < 32; ++r)
        Hp[(size_t)r * HID] = wmma::__float_to_tf32(fmaxf(scr[r*36 + lane] + bv, 0.0f));
      __syncwarp();
    }
  }
}

// ---------------- FFN layer 2: Y[padded row] = gate * (H @ W2[e] + b2[e]) ----------------
__global__ __launch_bounds__(NTHR) void k_ffn2(const float* __restrict__ b2)
{
  __shared__ __align__(16) float sm[2*BM*SA + 2*BK*SB];
  __shared__ float sGate[BM];

  const int tileStart = blockIdx.y * BM;
  if (tileStart >= g_poff[NE]) return;
  int e = 0;
#pragma unroll
  for (int i = 1; i < NE; ++i) if (tileStart >= g_poff[i]) e = i;
  const int posBase = tileStart - g_poff[e];
  const int cnt = g_count[e];
  const int tid = threadIdx.x;

  for (int r = tid; r < BM; r += NTHR) {
    int p = posBase + r;
    sGate[r] = (p < cnt) ? g_gate[e * TOK + p] : 0.0f;
  }
  __syncthreads();

  const int cBase = blockIdx.x * BN;
  const float* Bp = g_W2r + (size_t)e * HID * DIM;
  const float* Ap = g_H + (size_t)tileStart * HID;
  float* const As0 = sm;
  float* const Bs0 = sm + 2*BM*SA;

  wmma::fragment<wmma::accumulator,16,16,8,float> acc[4][4];
#pragma unroll
  for (int i = 0; i < 4; ++i)
#pragma unroll
    for (int j = 0; j < 4; ++j) wmma::fill_fragment(acc[i][j], 0.0f);

  const int warpId = tid >> 5, lane = tid & 31;
  const int wm = warpId & 1, wn = warpId >> 1;

  auto load_tile = [&](int stage, int kt) {
    float* As = As0 + stage * (BM*SA);
    float* Bs = Bs0 + stage * (BK*SB);
    const int k0 = kt * BK;
#pragma unroll
    for (int c = tid; c < (BM*BK)/4; c += NTHR) {
      int row = c >> 2, seg = c & 3;
      cp_async16(As + row*SA + seg*4, Ap + (size_t)row*HID + k0 + seg*4);
    }
#pragma unroll
    for (int c = tid; c < (BK*BN)/4; c += NTHR) {
      int row = c >> 5, seg = c & 31;
      cp_async16(Bs + row*SB + seg*4, Bp + (size_t)(k0+row)*DIM + cBase + seg*4);
    }
    CP_COMMIT();
  };

  const int KT = HID / BK;   // 128
  load_tile(0, 0);
  for (int kt = 0; kt < KT; ++kt) {
    if (kt + 1 < KT) { load_tile((kt+1)&1, kt+1); CP_WAIT(1); }
    else             { CP_WAIT(0); }
    __syncthreads();
    const float* As = As0 + (kt&1)*(BM*SA);
    const float* Bs = Bs0 + (kt&1)*(BK*SB);
#pragma unroll
    for (int kk = 0; kk < BK; kk += 8) {
      wmma::fragment<wmma::matrix_a,16,16,8,wmma::precision::tf32,wmma::row_major> af[4];
      wmma::fragment<wmma::matrix_b,16,16,8,wmma::precision::tf32,wmma::row_major> bf[4];
#pragma unroll
      for (int mi = 0; mi < 4; ++mi)
        wmma::load_matrix_sync(af[mi], As + (wm*64 + mi*16)*SA + kk, SA);
#pragma unroll
      for (int ni = 0; ni < 4; ++ni)
        wmma::load_matrix_sync(bf[ni], Bs + kk*SB + wn*64 + ni*16, SB);
#pragma unroll
      for (int mi = 0; mi < 4; ++mi)
#pragma unroll
        for (int ni = 0; ni < 4; ++ni)
          wmma::mma_sync(acc[mi][ni], af[mi], bf[ni], acc[mi][ni]);
    }
    __syncthreads();
  }

  // epilogue: gate * (acc + b2) -> plain stores into padded Y (pad rows store 0, never read)
  float* scr = sm + warpId * (32*36);
#pragma unroll
  for (int h = 0; h < 2; ++h) {
#pragma unroll
    for (int g = 0; g < 2; ++g) {
      wmma::store_matrix_sync(scr,              acc[2*h  ][2*g  ], 36, wmma::mem_row_major);
      wmma::store_matrix_sync(scr + 16,         acc[2*h  ][2*g+1], 36, wmma::mem_row_major);
      wmma::store_matrix_sync(scr + 16*36,      acc[2*h+1][2*g  ], 36, wmma::mem_row_major);
      wmma::store_matrix_sync(scr + 16*36 + 16, acc[2*h+1][2*g+1], 36, wmma::mem_row_major);
      __syncwarp();
      const int col = cBase + wn*64 + g*32 + lane;
      const float bv = b2[(size_t)e*DIM + col];
      float* Yp = g_Y + (size_t)(tileStart + wm*64 + h*32)*DIM + col;
#pragma unroll 8
      for (int r = 0; r < 32; ++r) {
        float gate = sGate[wm*64 + h*32 + r];
        Yp[(size_t)r * DIM] = gate * (scr[r*36 + lane] + bv);
      }
      __syncwarp();
    }
  }
}

// ---------------- final gather: out[t] = Y[row(top1)] + Y[row(top2)] ----------------
__global__ __launch_bounds__(256) void k_final(float* __restrict__ out) {
  const int idx = blockIdx.x * 256 + threadIdx.x;     // TOK*256 threads, float4 each
  const int t = idx >> 8, q = idx & 255;
  const int raw1 = g_slot1[t], raw2 = g_slot2[t];
  const int r1 = g_poff[raw1 >> 14] + (raw1 & (TOK - 1));
  const int r2 = g_poff[raw2 >> 14] + (raw2 & (TOK - 1));
  const float4* Y4 = (const float4*)g_Y;
  float4 a = Y4[(size_t)r1 * 256 + q];
  float4 b = Y4[(size_t)r2 * 256 + q];
  float4 o;
  o.x = a.x + b.x; o.y = a.y + b.y; o.z = a.z + b.z; o.w = a.w + b.w;
  ((float4*)out)[(size_t)t * 256 + q] = o;
}

// ---------------- launcher ----------------
extern "C" void kernel_launch(void* const* d_in, const int* in_sizes, int n_in,
                              void* d_out, int out_size) {
  const float* x  = (const float*)d_in[0];
  const float* Wg = (const float*)d_in[1];
  const float* bg = (const float*)d_in[2];
  const float* W1 = (const float*)d_in[3];
  const float* b1 = (const float*)d_in[4];
  const float* W2 = (const float*)d_in[5];
  const float* b2 = (const float*)d_in[6];
  float* out = (float*)d_out;
  (void)in_sizes; (void)n_in; (void)out_size;

  float *dW1r, *dW2r;
  cudaGetSymbolAddress((void**)&dW1r, g_W1r);
  cudaGetSymbolAddress((void**)&dW2r, g_W2r);

  k_init<<<1, 32>>>();
  k_router<<<TOK / 8, 256>>>(x, Wg, bg);
  k_round<<<4096, 256>>>(dW1r, W1, (NE * DIM * HID) / 4);
  k_round<<<4096, 256>>>(dW2r, W2, (NE * HID * DIM) / 4);
  k_scan<<<1, 32>>>();
  dim3 g1(HID / BN, ROWTILES);   // 16 x 264
  k_ffn1<<<g1, NTHR>>>(b1);
  dim3 g2(DIM / BN, ROWTILES);   // 8 x 264
  k_ffn2<<<g2, NTHR>>>(b2);
  k_final<<<TOK, 256>>>(out);
}